// round 11
// baseline (speedup 1.0000x reference)
#include <cuda_runtime.h>
#include <cuda_bf16.h>
#include <cstdint>

// y[b] = a_0 + sum_n bk[n] * tanh( dot(ck[n,:], z[b,:]) + dk[n] )
// B = 2097152, Z = 16, N = 64.
//
// HMMA m16n8k16 bf16, bf16x3 split, fp32 accum, dk in C init.
// This round: 3 sub-chunks (48 rows) in flight per warp-iteration at occ 2 —
// B-fragment LDS.128 and dk/bk broadcast loads amortized 3x, and 3 independent
// MMA->tanh chains give in-warp ILP to replace the lost occupancy.

#define ZD    16
#define NN    64
#define TPB   256
#define WPB   8
#define GRIDB 296      // 148 SMs * 2 CTAs: one persistent wave
#define CHUNK 16       // rows per sub-chunk; 3 sub-chunks per warp-iteration

static __device__ __forceinline__ float tanh_fast(float x) {
    float y; asm("tanh.approx.f32 %0, %1;" : "=f"(y) : "f"(x)); return y;
}
static __device__ __forceinline__ uint32_t pack_bf16x2(float lo, float hi) {
    uint32_t r; asm("cvt.rn.bf16x2.f32 %0, %1, %2;" : "=r"(r) : "f"(hi), "f"(lo)); return r;
}
static __device__ __forceinline__ float bf_lo_f(uint32_t h) { return __uint_as_float(h << 16); }
static __device__ __forceinline__ float bf_hi_f(uint32_t h) { return __uint_as_float(h & 0xFFFF0000u); }

static __device__ __forceinline__ void split2(float x, float y, uint32_t& h, uint32_t& l) {
    h = pack_bf16x2(x, y);
    l = pack_bf16x2(x - bf_lo_f(h), y - bf_hi_f(h));
}

static __device__ __forceinline__ void mma_bf16(
    float& d0, float& d1, float& d2, float& d3,
    uint32_t a0, uint32_t a1, uint32_t a2, uint32_t a3,
    uint32_t b0, uint32_t b1)
{
    asm volatile(
        "mma.sync.aligned.m16n8k16.row.col.f32.bf16.bf16.f32 "
        "{%0,%1,%2,%3}, {%4,%5,%6,%7}, {%8,%9}, {%0,%1,%2,%3};"
        : "+f"(d0), "+f"(d1), "+f"(d2), "+f"(d3)
        : "r"(a0), "r"(a1), "r"(a2), "r"(a3), "r"(b0), "r"(b1));
}

__global__ __launch_bounds__(TPB, 2)
void mave_hmma_kernel(const float2* __restrict__ zp,
                      const float* __restrict__ a0p,
                      const float* __restrict__ bkp,
                      const float* __restrict__ ckp,
                      const float* __restrict__ dkp,
                      float*       __restrict__ out,
                      int B, int nchunks)
{
    __shared__ uint4  sfrag[8][32];  // [j][lane] = (bh0, bh1, bl0, bl1), 4 KB
    __shared__ float4 sdb[8][4];     // [j][tg] = (dk0, dk1, bk0, bk1), 512 B

    const int tid  = threadIdx.x;
    const int wid  = tid >> 5;
    const int lane = tid & 31;
    const int g    = lane >> 2;
    const int tg   = lane & 3;

    // warp w builds the B fragment for j = w (identical across blocks)
    {
        const int j = wid;
        const float2* cp = reinterpret_cast<const float2*>(ckp + (8 * j + g) * ZD);
        float2 x0 = cp[tg];
        float2 x1 = cp[tg + 4];
        uint32_t h0, l0, h1, l1;
        split2(x0.x, x0.y, h0, l0);
        split2(x1.x, x1.y, h1, l1);
        sfrag[j][lane] = make_uint4(h0, h1, l0, l1);
    }
    if (tid < 32) {
        int j = tid >> 2, t = tid & 3;
        sdb[j][t] = make_float4(dkp[8 * j + 2 * t], dkp[8 * j + 2 * t + 1],
                                bkp[8 * j + 2 * t], bkp[8 * j + 2 * t + 1]);
    }
    __syncthreads();

    const float a0v = a0p[0];
    const int W    = GRIDB * WPB;   // 2368 warps total
    const int step = 3 * W;
    const int Bm1  = B - 1;

    int c = blockIdx.x * WPB + wid;
    if (c >= nchunks) return;

    // ---- prime: load 3 sub-chunk z buffers (chunk index clamped, rows clamped) ----
    float2 zb[3][4];
    #pragma unroll
    for (int s = 0; s < 3; s++) {
        int cc = c + s * W; if (cc > nchunks - 1) cc = 0;
        int base = cc * CHUNK;
        int r0 = base + g;     if (r0 > Bm1) r0 = Bm1;
        int r1 = base + g + 8; if (r1 > Bm1) r1 = Bm1;
        zb[s][0] = zp[r0 * 8 + tg];
        zb[s][1] = zp[r1 * 8 + tg];
        zb[s][2] = zp[r0 * 8 + tg + 4];
        zb[s][3] = zp[r1 * 8 + tg + 4];
    }

    while (c < nchunks) {
        const int c0 = c, c1 = c + W, c2 = c + 2 * W;

        // ---- consume buffers: bf16 hi/lo split into A fragments ----
        uint32_t AH[3][4], AL[3][4];
        #pragma unroll
        for (int s = 0; s < 3; s++) {
            split2(zb[s][0].x, zb[s][0].y, AH[s][0], AL[s][0]);
            split2(zb[s][1].x, zb[s][1].y, AH[s][1], AL[s][1]);
            split2(zb[s][2].x, zb[s][2].y, AH[s][2], AL[s][2]);
            split2(zb[s][3].x, zb[s][3].y, AH[s][3], AL[s][3]);
        }

        // ---- prefetch next triple (overlaps the whole compute body) ----
        const int cnext = c + step;
        #pragma unroll
        for (int s = 0; s < 3; s++) {
            int cc = cnext + s * W; if (cc > nchunks - 1) cc = 0;
            int base = cc * CHUNK;
            int r0 = base + g;     if (r0 > Bm1) r0 = Bm1;
            int r1 = base + g + 8; if (r1 > Bm1) r1 = Bm1;
            zb[s][0] = zp[r0 * 8 + tg];
            zb[s][1] = zp[r1 * 8 + tg];
            zb[s][2] = zp[r0 * 8 + tg + 4];
            zb[s][3] = zp[r1 * 8 + tg + 4];
        }

        float accL[3] = {0.f, 0.f, 0.f};
        float accH[3] = {0.f, 0.f, 0.f};

        #pragma unroll
        for (int j = 0; j < 8; j++) {
            const uint4  f  = sfrag[j][lane];   // one LDS.128 per j per 3 chunks
            const float4 db = sdb[j][tg];       // broadcast LDS.128

            #pragma unroll
            for (int s = 0; s < 3; s++) {
                float d0 = db.x, d1 = db.y, d2 = db.x, d3 = db.y;
                mma_bf16(d0, d1, d2, d3, AH[s][0], AH[s][1], AH[s][2], AH[s][3], f.x, f.y);
                mma_bf16(d0, d1, d2, d3, AL[s][0], AL[s][1], AL[s][2], AL[s][3], f.x, f.y);
                mma_bf16(d0, d1, d2, d3, AH[s][0], AH[s][1], AH[s][2], AH[s][3], f.z, f.w);

                accL[s] = fmaf(db.z, tanh_fast(d0), accL[s]);
                accL[s] = fmaf(db.w, tanh_fast(d1), accL[s]);
                accH[s] = fmaf(db.z, tanh_fast(d2), accH[s]);
                accH[s] = fmaf(db.w, tanh_fast(d3), accH[s]);
            }
        }

        // ---- reduce over the 4 column-threads, store ----
        #pragma unroll
        for (int s = 0; s < 3; s++) {
            accL[s] += __shfl_xor_sync(0xFFFFFFFFu, accL[s], 1);
            accL[s] += __shfl_xor_sync(0xFFFFFFFFu, accL[s], 2);
            accH[s] += __shfl_xor_sync(0xFFFFFFFFu, accH[s], 1);
            accH[s] += __shfl_xor_sync(0xFFFFFFFFu, accH[s], 2);
        }

        if (tg == 0) {
            const int cs[3] = {c0, c1, c2};
            #pragma unroll
            for (int s = 0; s < 3; s++) {
                if (cs[s] < nchunks) {
                    int base = cs[s] * CHUNK;
                    if (base + g < B)     out[base + g]     = a0v + accL[s];
                    if (base + g + 8 < B) out[base + g + 8] = a0v + accH[s];
                }
            }
        }
        c = cnext;
    }
}

extern "C" void kernel_launch(void* const* d_in, const int* in_sizes, int n_in,
                              void* d_out, int out_size) {
    const float* z  = (const float*)d_in[0];
    const float* a0 = (const float*)d_in[1];
    const float* bk = (const float*)d_in[2];
    const float* ck = (const float*)d_in[3];
    const float* dk = (const float*)d_in[4];
    float* out = (float*)d_out;

    const int B = in_sizes[0] / ZD;
    const int nchunks = (B + CHUNK - 1) / CHUNK;

    mave_hmma_kernel<<<GRIDB, TPB>>>((const float2*)z, a0, bk, ck, dk, out, B, nchunks);
}